// round 16
// baseline (speedup 1.0000x reference)
#include <cuda_runtime.h>
#include <cuda_bf16.h>
#include <cuda_fp16.h>

// Damping_27066883900008 R16: R6 structure (best total 84.5us) with every
// tanh pair computed via ONE tanh.approx.f16x2 instead of two scalar
// tanh.approx.f32: MUFU inst/warp halves (1024->512 cyc), removing the
// co-critical MUFU stream + halving the layer-3 MUFU burst. FMA stream,
// launch shape (256 x 2 CTAs), and constant-bank LDCU weights unchanged.

#define NTHREADS 256
typedef unsigned long long ull;

struct __align__(16) Params {
    ull   w2p[256];    // (16,16) packed {wd2, wo2}, 16B-aligned pairs
    ull   w1p[32];     // (2,16)  packed {wd1, wo1}
    ull   b1p[16];     // {bd1, bo1}
    ull   b2p[16];     // {bd2, bo2}
    ull   wd3ap[16];   // {wd3[k][0], wd3[k][0]}
    ull   wd3bp[16];   // {wd3[k][1], wd3[k][1]}
    ull   wo3p[16];    // {wo3[k],    wo3[k]}
    ull   bd30p, bd31p, bo3p;
};

__device__    Params g_pack;
__constant__  Params c_p;

__device__ __forceinline__ ull pack2(float lo, float hi) {
    ull r; asm("mov.b64 %0, {%1, %2};" : "=l"(r) : "f"(lo), "f"(hi)); return r;
}
__device__ __forceinline__ void unpack2(ull v, float& lo, float& hi) {
    asm("mov.b64 {%0, %1}, %2;" : "=f"(lo), "=f"(hi) : "l"(v));
}
__device__ __forceinline__ ull fma2(ull a, ull b, ull c) {
    ull d; asm("fma.rn.f32x2 %0, %1, %2, %3;" : "=l"(d) : "l"(a), "l"(b), "l"(c)); return d;
}
__device__ __forceinline__ ull mul2(ull a, ull b) {
    ull d; asm("mul.rn.f32x2 %0, %1, %2;" : "=l"(d) : "l"(a), "l"(b)); return d;
}
__device__ __forceinline__ ull add2(ull a, ull b) {
    ull d; asm("add.rn.f32x2 %0, %1, %2;" : "=l"(d) : "l"(a), "l"(b)); return d;
}
__device__ __forceinline__ float tanh_ap(float x) {
    float y; asm("tanh.approx.f32 %0, %1;" : "=f"(y) : "f"(x)); return y;
}

// Packed tanh of a f32x2 pair via ONE tanh.approx.f16x2 MUFU op.
// f32x2 -> f16x2 (1 cvt) -> tanh.f16x2 (1 MUFU) -> f32x2 (2 cvt).
__device__ __forceinline__ ull tanh2h(ull v) {
    float lo, hi; unpack2(v, lo, hi);
    unsigned h2;
    asm("cvt.rn.f16x2.f32 %0, %1, %2;" : "=r"(h2) : "f"(hi), "f"(lo));
    asm("tanh.approx.f16x2 %0, %0;" : "+r"(h2));
    float rlo, rhi;
    asm("{ .reg .b16 l, h;\n\t"
        "  mov.b32 {l, h}, %2;\n\t"
        "  cvt.f32.f16 %0, l;\n\t"
        "  cvt.f32.f16 %1, h; }"
        : "=f"(rlo), "=f"(rhi) : "r"(h2));
    return pack2(rlo, rhi);
}

__global__ void pack_kernel(
    const float* __restrict__ w_d1, const float* __restrict__ w_d2,
    const float* __restrict__ w_d3, const float* __restrict__ w_o1,
    const float* __restrict__ w_o2, const float* __restrict__ w_o3,
    const float* __restrict__ b_d1, const float* __restrict__ b_d2,
    const float* __restrict__ b_d3, const float* __restrict__ b_o1,
    const float* __restrict__ b_o2, const float* __restrict__ b_o3)
{
    const int t = threadIdx.x;
    if (t < 256) g_pack.w2p[t] = pack2(w_d2[t], w_o2[t]);
    if (t < 32)  g_pack.w1p[t] = pack2(w_d1[t], w_o1[t]);
    if (t < 16)  {
        g_pack.b1p[t]   = pack2(b_d1[t], b_o1[t]);
        g_pack.b2p[t]   = pack2(b_d2[t], b_o2[t]);
        g_pack.wd3ap[t] = pack2(w_d3[t * 2 + 0], w_d3[t * 2 + 0]);
        g_pack.wd3bp[t] = pack2(w_d3[t * 2 + 1], w_d3[t * 2 + 1]);
        g_pack.wo3p[t]  = pack2(w_o3[t], w_o3[t]);
    }
    if (t == 0) {
        g_pack.bd30p = pack2(b_d3[0], b_d3[0]);
        g_pack.bd31p = pack2(b_d3[1], b_d3[1]);
        g_pack.bo3p  = pack2(b_o3[0], b_o3[0]);
    }
}

__global__ __launch_bounds__(NTHREADS, 2) void damping_kernel(
    const float4* __restrict__ x, float4* __restrict__ out, int npairs)
{
    const int p = blockIdx.x * NTHREADS + threadIdx.x;
    if (p >= npairs) return;

    // Two adjacent rows per thread: A = 2p, B = 2p+1 -> one float4.
    const float4 xi = x[p];
    const ull x0A = pack2(xi.x, xi.x), x1A = pack2(xi.y, xi.y);
    const ull x0B = pack2(xi.z, xi.z), x1B = pack2(xi.w, xi.w);

    // ---------------- fused layer-1 + layer-2 (packed {d,o}) ----------------
    ull accA[16], accB[16];
    #pragma unroll
    for (int j = 0; j < 16; j++) { accA[j] = c_p.b2p[j]; accB[j] = accA[j]; }

    #pragma unroll
    for (int k = 0; k < 16; k++) {
        const ull w1k0 = c_p.w1p[k];
        const ull w1k1 = c_p.w1p[16 + k];
        const ull b1k  = c_p.b1p[k];
        const ull hA = tanh2h(fma2(x0A, w1k0, fma2(x1A, w1k1, b1k)));
        const ull hB = tanh2h(fma2(x0B, w1k0, fma2(x1B, w1k1, b1k)));

        #pragma unroll
        for (int j2 = 0; j2 < 8; j2++) {
            // 16B-aligned pair -> LDCU.128 eligible
            const ulonglong2 w =
                *reinterpret_cast<const ulonglong2*>(&c_p.w2p[k * 16 + j2 * 2]);
            accA[j2 * 2 + 0] = fma2(hA, w.x, accA[j2 * 2 + 0]);
            accA[j2 * 2 + 1] = fma2(hA, w.y, accA[j2 * 2 + 1]);
            accB[j2 * 2 + 0] = fma2(hB, w.x, accB[j2 * 2 + 0]);
            accB[j2 * 2 + 1] = fma2(hB, w.y, accB[j2 * 2 + 1]);
        }
    }

    // ---------------- layer 3 (packed {A,B}) ----------------
    ull d30p = c_p.bd30p, d31p = c_p.bd31p, cp = c_p.bo3p;
    #pragma unroll
    for (int k = 0; k < 16; k++) {
        float pdA, poA; unpack2(accA[k], pdA, poA);
        float pdB, poB; unpack2(accB[k], pdB, poB);
        const ull gdp = tanh2h(pack2(pdA, pdB));
        const ull gop = tanh2h(pack2(poA, poB));
        d30p = fma2(gdp, c_p.wd3ap[k], d30p);
        d31p = fma2(gdp, c_p.wd3bp[k], d31p);
        cp   = fma2(gop, c_p.wo3p[k],  cp);
    }

    // ---------------- damping-matrix epilogue (packed {A,B}) ----------------
    float d30A, d30B, d31A, d31B;
    unpack2(d30p, d30A, d30B);
    unpack2(d31p, d31A, d31B);

    const ull x0p = pack2(xi.x, xi.z);            // {x0_A, x0_B}
    const ull x1p = pack2(xi.y, xi.w);            // {x1_A, x1_B}
    const ull k001 = pack2(0.001f, 0.001f);

    const ull r0 = pack2(fmaxf(d30A, 0.0f), fmaxf(d30B, 0.0f));
    const ull r1 = pack2(fmaxf(d31A, 0.0f), fmaxf(d31B, 0.0f));
    const ull ap = mul2(add2(r0, k001), x0p);     // a = (relu(d30)+eps)*x0
    const ull bp = mul2(add2(r1, k001), x1p);     // b = (relu(d31)+eps)*x1

    const ull acp  = mul2(ap, cp);
    const ull aap  = mul2(ap, ap);
    const ull ccbb = fma2(cp, cp, mul2(bp, bp));
    const ull D0p  = fma2(aap, x0p, mul2(acp, x1p));
    const ull D1p  = fma2(acp, x0p, mul2(ccbb, x1p));

    float4 o;
    float D0A, D0B, D1A, D1B;
    unpack2(D0p, D0A, D0B);
    unpack2(D1p, D1A, D1B);
    o.x = D0A; o.y = D1A; o.z = D0B; o.w = D1B;
    out[p] = o;
}

extern "C" void kernel_launch(void* const* d_in, const int* in_sizes, int n_in,
                              void* d_out, int out_size) {
    const float4* x   = (const float4*)d_in[0];
    const float* w_d1 = (const float*)d_in[1];
    const float* w_d2 = (const float*)d_in[2];
    const float* w_d3 = (const float*)d_in[3];
    const float* w_o1 = (const float*)d_in[4];
    const float* w_o2 = (const float*)d_in[5];
    const float* w_o3 = (const float*)d_in[6];
    const float* b_d1 = (const float*)d_in[7];
    const float* b_d2 = (const float*)d_in[8];
    const float* b_d3 = (const float*)d_in[9];
    const float* b_o1 = (const float*)d_in[10];
    const float* b_o2 = (const float*)d_in[11];
    const float* b_o3 = (const float*)d_in[12];
    float4* out = (float4*)d_out;

    // 1) pack weights into __device__ scratch
    pack_kernel<<<1, 256>>>(w_d1, w_d2, w_d3, w_o1, w_o2, w_o3,
                            b_d1, b_d2, b_d3, b_o1, b_o2, b_o3);

    // 2) D2D copy scratch -> constant bank (graph-capturable memcpy node)
    void* src = nullptr;
    cudaGetSymbolAddress(&src, g_pack);
    cudaMemcpyToSymbolAsync(c_p, src, sizeof(Params), 0,
                            cudaMemcpyDeviceToDevice, 0);

    // 3) main kernel
    const int nrows  = in_sizes[0] / 2;
    const int npairs = nrows / 2;               // B = 4194304 is even
    const int grid   = (npairs + NTHREADS - 1) / NTHREADS;
    damping_kernel<<<grid, NTHREADS>>>(x, out, npairs);
}

// round 17
// speedup vs baseline: 1.2693x; 1.2693x over previous
#include <cuda_runtime.h>
#include <cuda_bf16.h>

// Damping_27066883900008 FINAL (= R6, certified best: 84.5us, rel_err 5.5e-6).
// - f32x2 {d-net,o-net} packing everywhere (FFMA2, full 128 MAC-lanes/cyc/SM)
// - weights in __constant__ via pack-kernel + D2D memcpyToSymbol (LDCU uniform
//   port: L1TEX 94.8% -> 4.4% vs shared-memory staging)
// - MUFU.TANH single-instruction activations
// - layer-3 + epilogue packed across the row pair {A,B}
// - 2 rows/thread, 256 threads x 2 CTAs/SM (empirical optimum of the
//   16/20/24/34-warp sweep; FMA busy invariant ~66.4us, exposure minimized)

#define NTHREADS 256
typedef unsigned long long ull;

struct __align__(16) Params {
    ull   w2p[256];    // (16,16) packed {wd2, wo2}, 16B-aligned pairs
    ull   w1p[32];     // (2,16)  packed {wd1, wo1}
    ull   b1p[16];     // {bd1, bo1}
    ull   b2p[16];     // {bd2, bo2}
    ull   wd3ap[16];   // {wd3[k][0], wd3[k][0]}  (dup for {A,B} fma2)
    ull   wd3bp[16];   // {wd3[k][1], wd3[k][1]}
    ull   wo3p[16];    // {wo3[k],    wo3[k]}
    ull   bd30p;       // {bd3[0], bd3[0]}
    ull   bd31p;       // {bd3[1], bd3[1]}
    ull   bo3p;        // {bo3[0], bo3[0]}
};

__device__    Params g_pack;   // scratch filled by prep kernel
__constant__  Params c_p;      // uniform-port home of the weights

__device__ __forceinline__ ull pack2(float lo, float hi) {
    ull r; asm("mov.b64 %0, {%1, %2};" : "=l"(r) : "f"(lo), "f"(hi)); return r;
}
__device__ __forceinline__ void unpack2(ull v, float& lo, float& hi) {
    asm("mov.b64 {%0, %1}, %2;" : "=f"(lo), "=f"(hi) : "l"(v));
}
__device__ __forceinline__ ull fma2(ull a, ull b, ull c) {
    ull d; asm("fma.rn.f32x2 %0, %1, %2, %3;" : "=l"(d) : "l"(a), "l"(b), "l"(c)); return d;
}
__device__ __forceinline__ ull mul2(ull a, ull b) {
    ull d; asm("mul.rn.f32x2 %0, %1, %2;" : "=l"(d) : "l"(a), "l"(b)); return d;
}
__device__ __forceinline__ ull add2(ull a, ull b) {
    ull d; asm("add.rn.f32x2 %0, %1, %2;" : "=l"(d) : "l"(a), "l"(b)); return d;
}
__device__ __forceinline__ float tanh_ap(float x) {
    float y; asm("tanh.approx.f32 %0, %1;" : "=f"(y) : "f"(x)); return y;
}
__device__ __forceinline__ ull tanh2(ull v) {
    float lo, hi; unpack2(v, lo, hi);
    return pack2(tanh_ap(lo), tanh_ap(hi));
}

__global__ void pack_kernel(
    const float* __restrict__ w_d1, const float* __restrict__ w_d2,
    const float* __restrict__ w_d3, const float* __restrict__ w_o1,
    const float* __restrict__ w_o2, const float* __restrict__ w_o3,
    const float* __restrict__ b_d1, const float* __restrict__ b_d2,
    const float* __restrict__ b_d3, const float* __restrict__ b_o1,
    const float* __restrict__ b_o2, const float* __restrict__ b_o3)
{
    const int t = threadIdx.x;
    if (t < 256) g_pack.w2p[t] = pack2(w_d2[t], w_o2[t]);
    if (t < 32)  g_pack.w1p[t] = pack2(w_d1[t], w_o1[t]);
    if (t < 16)  {
        g_pack.b1p[t]   = pack2(b_d1[t], b_o1[t]);
        g_pack.b2p[t]   = pack2(b_d2[t], b_o2[t]);
        g_pack.wd3ap[t] = pack2(w_d3[t * 2 + 0], w_d3[t * 2 + 0]);
        g_pack.wd3bp[t] = pack2(w_d3[t * 2 + 1], w_d3[t * 2 + 1]);
        g_pack.wo3p[t]  = pack2(w_o3[t], w_o3[t]);
    }
    if (t == 0) {
        g_pack.bd30p = pack2(b_d3[0], b_d3[0]);
        g_pack.bd31p = pack2(b_d3[1], b_d3[1]);
        g_pack.bo3p  = pack2(b_o3[0], b_o3[0]);
    }
}

__global__ __launch_bounds__(NTHREADS, 2) void damping_kernel(
    const float4* __restrict__ x, float4* __restrict__ out, int npairs)
{
    const int p = blockIdx.x * NTHREADS + threadIdx.x;
    if (p >= npairs) return;

    // Two adjacent rows per thread: A = 2p, B = 2p+1 -> one float4.
    const float4 xi = x[p];
    const ull x0A = pack2(xi.x, xi.x), x1A = pack2(xi.y, xi.y);
    const ull x0B = pack2(xi.z, xi.z), x1B = pack2(xi.w, xi.w);

    // ---------------- fused layer-1 + layer-2 (packed {d,o}) ----------------
    ull accA[16], accB[16];
    #pragma unroll
    for (int j = 0; j < 16; j++) { accA[j] = c_p.b2p[j]; accB[j] = accA[j]; }

    #pragma unroll
    for (int k = 0; k < 16; k++) {
        const ull w1k0 = c_p.w1p[k];
        const ull w1k1 = c_p.w1p[16 + k];
        const ull b1k  = c_p.b1p[k];
        const ull hA = tanh2(fma2(x0A, w1k0, fma2(x1A, w1k1, b1k)));
        const ull hB = tanh2(fma2(x0B, w1k0, fma2(x1B, w1k1, b1k)));

        #pragma unroll
        for (int j2 = 0; j2 < 8; j2++) {
            // 16B-aligned pair -> LDCU.128 eligible
            const ulonglong2 w =
                *reinterpret_cast<const ulonglong2*>(&c_p.w2p[k * 16 + j2 * 2]);
            accA[j2 * 2 + 0] = fma2(hA, w.x, accA[j2 * 2 + 0]);
            accA[j2 * 2 + 1] = fma2(hA, w.y, accA[j2 * 2 + 1]);
            accB[j2 * 2 + 0] = fma2(hB, w.x, accB[j2 * 2 + 0]);
            accB[j2 * 2 + 1] = fma2(hB, w.y, accB[j2 * 2 + 1]);
        }
    }

    // ---------------- layer 3 (packed {A,B}) ----------------
    ull d30p = c_p.bd30p, d31p = c_p.bd31p, cp = c_p.bo3p;
    #pragma unroll
    for (int k = 0; k < 16; k++) {
        float pdA, poA; unpack2(accA[k], pdA, poA);
        float pdB, poB; unpack2(accB[k], pdB, poB);
        const ull gdp = pack2(tanh_ap(pdA), tanh_ap(pdB));
        const ull gop = pack2(tanh_ap(poA), tanh_ap(poB));
        d30p = fma2(gdp, c_p.wd3ap[k], d30p);
        d31p = fma2(gdp, c_p.wd3bp[k], d31p);
        cp   = fma2(gop, c_p.wo3p[k],  cp);
    }

    // ---------------- damping-matrix epilogue (packed {A,B}) ----------------
    float d30A, d30B, d31A, d31B;
    unpack2(d30p, d30A, d30B);
    unpack2(d31p, d31A, d31B);

    const ull x0p = pack2(xi.x, xi.z);            // {x0_A, x0_B}
    const ull x1p = pack2(xi.y, xi.w);            // {x1_A, x1_B}
    const ull k001 = pack2(0.001f, 0.001f);

    const ull r0 = pack2(fmaxf(d30A, 0.0f), fmaxf(d30B, 0.0f));
    const ull r1 = pack2(fmaxf(d31A, 0.0f), fmaxf(d31B, 0.0f));
    const ull ap = mul2(add2(r0, k001), x0p);     // a = (relu(d30)+eps)*x0
    const ull bp = mul2(add2(r1, k001), x1p);     // b = (relu(d31)+eps)*x1

    const ull acp  = mul2(ap, cp);
    const ull aap  = mul2(ap, ap);
    const ull ccbb = fma2(cp, cp, mul2(bp, bp));
    const ull D0p  = fma2(aap, x0p, mul2(acp, x1p));
    const ull D1p  = fma2(acp, x0p, mul2(ccbb, x1p));

    float4 o;
    float D0A, D0B, D1A, D1B;
    unpack2(D0p, D0A, D0B);
    unpack2(D1p, D1A, D1B);
    o.x = D0A; o.y = D1A; o.z = D0B; o.w = D1B;
    out[p] = o;
}

extern "C" void kernel_launch(void* const* d_in, const int* in_sizes, int n_in,
                              void* d_out, int out_size) {
    const float4* x   = (const float4*)d_in[0];
    const float* w_d1 = (const float*)d_in[1];
    const float* w_d2 = (const float*)d_in[2];
    const float* w_d3 = (const float*)d_in[3];
    const float* w_o1 = (const float*)d_in[4];
    const float* w_o2 = (const float*)d_in[5];
    const float* w_o3 = (const float*)d_in[6];
    const float* b_d1 = (const float*)d_in[7];
    const float* b_d2 = (const float*)d_in[8];
    const float* b_d3 = (const float*)d_in[9];
    const float* b_o1 = (const float*)d_in[10];
    const float* b_o2 = (const float*)d_in[11];
    const float* b_o3 = (const float*)d_in[12];
    float4* out = (float4*)d_out;

    // 1) pack weights into __device__ scratch
    pack_kernel<<<1, 256>>>(w_d1, w_d2, w_d3, w_o1, w_o2, w_o3,
                            b_d1, b_d2, b_d3, b_o1, b_o2, b_o3);

    // 2) D2D copy scratch -> constant bank (graph-capturable memcpy node)
    void* src = nullptr;
    cudaGetSymbolAddress(&src, g_pack);
    cudaMemcpyToSymbolAsync(c_p, src, sizeof(Params), 0,
                            cudaMemcpyDeviceToDevice, 0);

    // 3) main kernel
    const int nrows  = in_sizes[0] / 2;
    const int npairs = nrows / 2;               // B = 4194304 is even
    const int grid   = (npairs + NTHREADS - 1) / NTHREADS;
    damping_kernel<<<grid, NTHREADS>>>(x, out, npairs);
}